// round 1
// baseline (speedup 1.0000x reference)
#include <cuda_runtime.h>
#include <cuda_bf16.h>
#include <math.h>

// ---------------- problem constants ----------------
#define NN      30000
#define IN_DIM  3000
#define DDIM    512     // DEG_DIM
#define HID     512
#define OUTD    30
#define PREDD   20
#define DEG     10
#define EDGES   (NN*DEG)
#define NEG_SLOPE 0.2f

// ---------------- scratch (static device memory; no allocs allowed) --------
__device__ float g_de [NN*DDIM];
__device__ float g_x1 [NN*HID];
__device__ float g_h1 [NN*HID];
__device__ float g_x3 [NN*HID];
__device__ float g_h3 [NN*HID];
__device__ float g_h4 [NN*DDIM];
__device__ float g_a1s[NN];
__device__ float g_a1d[NN];
__device__ float g_alpha[EDGES];
__device__ float g_W1T[HID*DDIM];   // W1^T : [HID, DDIM] -> transpose of W1 [DDIM,HID]
__device__ float g_W2T[OUTD*HID];   // W2^T : [OUTD, HID]

// ---------------- tiled SGEMM: C[M,N] = A[M,K] @ B[K,N] (+bias) ------------
#define BM 128
#define BN 128
#define BK 8
#define TM 8
#define TN 8

__global__ __launch_bounds__(256) void sgemm_kernel(
    const float* __restrict__ A, const float* __restrict__ B,
    const float* __restrict__ bias, float* __restrict__ C,
    int M, int N, int K)
{
    __shared__ float As[BK][BM];
    __shared__ float Bs[BK][BN + 4];

    const int tid  = threadIdx.x;
    const int row0 = blockIdx.y * BM;
    const int col0 = blockIdx.x * BN;
    const int trow = (tid >> 4) * TM;   // 16 thread-rows
    const int tcol = (tid & 15) * TN;   // 16 thread-cols

    float acc[TM][TN];
    #pragma unroll
    for (int i = 0; i < TM; i++)
        #pragma unroll
        for (int j = 0; j < TN; j++) acc[i][j] = 0.f;

    for (int k0 = 0; k0 < K; k0 += BK) {
        // A tile: BM x BK
        #pragma unroll
        for (int s = 0; s < 4; s++) {
            int idx = tid + s * 256;          // 0..1023
            int r = idx >> 3, c = idx & 7;
            int gr = row0 + r, gc = k0 + c;
            As[c][r] = (gr < M && gc < K) ? A[(size_t)gr * K + gc] : 0.f;
        }
        // B tile: BK x BN (coalesced)
        #pragma unroll
        for (int s = 0; s < 4; s++) {
            int idx = tid + s * 256;
            int r = idx >> 7, c = idx & 127;
            int gr = k0 + r, gc = col0 + c;
            Bs[r][c] = (gr < K && gc < N) ? B[(size_t)gr * N + gc] : 0.f;
        }
        __syncthreads();

        #pragma unroll
        for (int k = 0; k < BK; k++) {
            float a[TM], b[TN];
            #pragma unroll
            for (int i = 0; i < TM; i++) a[i] = As[k][trow + i];
            #pragma unroll
            for (int j = 0; j < TN; j++) b[j] = Bs[k][tcol + j];
            #pragma unroll
            for (int i = 0; i < TM; i++)
                #pragma unroll
                for (int j = 0; j < TN; j++)
                    acc[i][j] += a[i] * b[j];
        }
        __syncthreads();
    }

    #pragma unroll
    for (int i = 0; i < TM; i++) {
        int gr = row0 + trow + i;
        if (gr >= M) continue;
        #pragma unroll
        for (int j = 0; j < TN; j++) {
            int gc = col0 + tcol + j;
            if (gc >= N) continue;
            float v = acc[i][j];
            if (bias) v += bias[gc];
            C[(size_t)gr * N + gc] = v;
        }
    }
}

// ---------------- transpose: in[R,C] -> out[C,R] ---------------------------
__global__ void transpose_kernel(const float* __restrict__ in,
                                 float* __restrict__ out, int R, int C)
{
    __shared__ float t[32][33];
    int c = blockIdx.x * 32 + threadIdx.x;
    int r = blockIdx.y * 32 + threadIdx.y;
    if (r < R && c < C) t[threadIdx.y][threadIdx.x] = in[r * C + c];
    __syncthreads();
    int r2 = blockIdx.x * 32 + threadIdx.y;   // output row (= original col)
    int c2 = blockIdx.y * 32 + threadIdx.x;   // output col (= original row)
    if (r2 < C && c2 < R) out[r2 * R + c2] = t[threadIdx.x][threadIdx.y];
}

// ---------------- per-row attention logits: a1s = x1 @ att_src etc ---------
__global__ void row_logits_kernel(const float* __restrict__ x1,
                                  const float* __restrict__ att_s,
                                  const float* __restrict__ att_d,
                                  float* __restrict__ a1s,
                                  float* __restrict__ a1d, int n)
{
    int row = blockIdx.x * 8 + threadIdx.y;
    if (row >= n) return;
    int lane = threadIdx.x;
    float s = 0.f, d = 0.f;
    const float* xr = x1 + (size_t)row * HID;
    #pragma unroll 4
    for (int k = lane; k < HID; k += 32) {
        float v = xr[k];
        s += v * att_s[k];
        d += v * att_d[k];
    }
    #pragma unroll
    for (int o = 16; o > 0; o >>= 1) {
        s += __shfl_down_sync(0xffffffffu, s, o);
        d += __shfl_down_sync(0xffffffffu, d, o);
    }
    if (lane == 0) { a1s[row] = s; a1d[row] = d; }
}

// ---------------- per-node edge softmax (segments are contiguous) ----------
__global__ void alpha_kernel(const int* __restrict__ src,
                             const int* __restrict__ dst,
                             const float* __restrict__ a1s,
                             const float* __restrict__ a1d,
                             float* __restrict__ alpha, int n)
{
    int i = blockIdx.x * 256 + threadIdx.x;
    if (i >= n) return;
    float e[DEG];
    float m = -1e30f;
    #pragma unroll
    for (int j = 0; j < DEG; j++) {
        int eidx = i * DEG + j;
        float v = a1s[src[eidx]] + a1d[dst[eidx]];
        v = (v > 0.f) ? v : NEG_SLOPE * v;      // leaky_relu
        e[j] = v;
        m = fmaxf(m, v);
    }
    float sum = 0.f;
    #pragma unroll
    for (int j = 0; j < DEG; j++) { e[j] = __expf(e[j] - m); sum += e[j]; }
    float inv = 1.f / sum;
    #pragma unroll
    for (int j = 0; j < DEG; j++) alpha[i * DEG + j] = e[j] * inv;
}

// ---------------- weighted aggregation + ELU: one block per node -----------
__global__ __launch_bounds__(128) void agg_elu_kernel(
    const float* __restrict__ x, const int* __restrict__ src,
    const float* __restrict__ alpha, float* __restrict__ out)
{
    int i = blockIdx.x;
    __shared__ int   ss[DEG];
    __shared__ float sa[DEG];
    if (threadIdx.x < DEG) {
        ss[threadIdx.x] = src[i * DEG + threadIdx.x];
        sa[threadIdx.x] = alpha[i * DEG + threadIdx.x];
    }
    __syncthreads();
    int c0 = threadIdx.x * 4;
    float a0 = 0.f, a1 = 0.f, a2 = 0.f, a3 = 0.f;
    #pragma unroll
    for (int j = 0; j < DEG; j++) {
        const float4 v = *(const float4*)&x[(size_t)ss[j] * HID + c0];
        float a = sa[j];
        a0 += a * v.x; a1 += a * v.y; a2 += a * v.z; a3 += a * v.w;
    }
    float4 r;
    r.x = (a0 > 0.f) ? a0 : expm1f(a0);
    r.y = (a1 > 0.f) ? a1 : expm1f(a1);
    r.z = (a2 > 0.f) ? a2 : expm1f(a2);
    r.w = (a3 > 0.f) ? a3 : expm1f(a3);
    *(float4*)&out[(size_t)i * HID + c0] = r;
}

// ---------------- prediction head: log_softmax(h2 @ W_pred + b_pred) -------
__global__ void pred_kernel(const float* __restrict__ h2,
                            const float* __restrict__ Wp,
                            const float* __restrict__ bp,
                            float* __restrict__ logp, int n)
{
    int i = blockIdx.x * 128 + threadIdx.x;
    if (i >= n) return;
    float h[OUTD];
    #pragma unroll
    for (int k = 0; k < OUTD; k++) h[k] = h2[(size_t)i * OUTD + k];
    float p[PREDD];
    float m = -1e30f;
    #pragma unroll
    for (int c = 0; c < PREDD; c++) {
        float s = bp[c];
        #pragma unroll
        for (int k = 0; k < OUTD; k++) s += h[k] * Wp[k * PREDD + c];
        p[c] = s;
        m = fmaxf(m, s);
    }
    float sum = 0.f;
    #pragma unroll
    for (int c = 0; c < PREDD; c++) sum += expf(p[c] - m);
    float lse = m + logf(sum);
    #pragma unroll
    for (int c = 0; c < PREDD; c++) logp[(size_t)i * PREDD + c] = p[c] - lse;
}

// ---------------- elementwise ELU (in place) --------------------------------
__global__ void elu_kernel(float* __restrict__ x, int n)
{
    int i = blockIdx.x * 256 + threadIdx.x;
    if (i >= n) return;
    float v = x[i];
    x[i] = (v > 0.f) ? v : expm1f(v);
}

// ---------------- launch ----------------------------------------------------
static inline dim3 gemm_grid(int M, int N) {
    return dim3((N + BN - 1) / BN, (M + BM - 1) / BM);
}

extern "C" void kernel_launch(void* const* d_in, const int* in_sizes, int n_in,
                              void* d_out, int out_size)
{
    const float* features = (const float*)d_in[0];
    const int*   edge     = (const int*)  d_in[1];
    const float* W_enc    = (const float*)d_in[2];
    const float* b_enc    = (const float*)d_in[3];
    const float* W1       = (const float*)d_in[4];
    const float* att_src  = (const float*)d_in[5];
    const float* att_dst  = (const float*)d_in[6];
    const float* W2       = (const float*)d_in[7];
    const float* W_pred   = (const float*)d_in[8];
    const float* b_pred   = (const float*)d_in[9];
    const float* W_dec    = (const float*)d_in[10];
    const float* b_dec    = (const float*)d_in[11];

    const int* src = edge;
    const int* dst = edge + EDGES;

    float* out  = (float*)d_out;
    float* h2   = out;                                // [N, 30]
    float* outm = out + (size_t)NN * OUTD;            // [N, 3000]
    float* logp = out + (size_t)NN * OUTD + (size_t)NN * IN_DIM;  // [N, 20]

    float *de, *x1, *h1, *x3, *h3, *h4, *a1s, *a1d, *alpha, *W1T, *W2T;
    cudaGetSymbolAddress((void**)&de,    g_de);
    cudaGetSymbolAddress((void**)&x1,    g_x1);
    cudaGetSymbolAddress((void**)&h1,    g_h1);
    cudaGetSymbolAddress((void**)&x3,    g_x3);
    cudaGetSymbolAddress((void**)&h3,    g_h3);
    cudaGetSymbolAddress((void**)&h4,    g_h4);
    cudaGetSymbolAddress((void**)&a1s,   g_a1s);
    cudaGetSymbolAddress((void**)&a1d,   g_a1d);
    cudaGetSymbolAddress((void**)&alpha, g_alpha);
    cudaGetSymbolAddress((void**)&W1T,   g_W1T);
    cudaGetSymbolAddress((void**)&W2T,   g_W2T);

    // tied-weight transposes (small)
    transpose_kernel<<<dim3((HID + 31) / 32, (DDIM + 31) / 32), dim3(32, 32)>>>(W1, W1T, DDIM, HID);
    transpose_kernel<<<dim3((OUTD + 31) / 32, (HID + 31) / 32), dim3(32, 32)>>>(W2, W2T, HID, OUTD);

    // 1. de = features @ W_enc + b_enc
    sgemm_kernel<<<gemm_grid(NN, DDIM), 256>>>(features, W_enc, b_enc, de, NN, DDIM, IN_DIM);
    // 2. x1 = de @ W1
    sgemm_kernel<<<gemm_grid(NN, HID), 256>>>(de, W1, nullptr, x1, NN, HID, DDIM);
    // 3. attention logits
    row_logits_kernel<<<(NN + 7) / 8, dim3(32, 8)>>>(x1, att_src, att_dst, a1s, a1d, NN);
    // 4. edge softmax (shared by conv1 and conv3)
    alpha_kernel<<<(NN + 255) / 256, 256>>>(src, dst, a1s, a1d, alpha, NN);
    // 5. h1 = elu(aggregate(x1))
    agg_elu_kernel<<<NN, 128>>>(x1, src, alpha, h1);
    // 6. h2 = h1 @ W2   (output 0)
    sgemm_kernel<<<gemm_grid(NN, OUTD), 256>>>(h1, W2, nullptr, h2, NN, OUTD, HID);
    // 7. log_softmax(h2 @ W_pred + b_pred)  (output 2)
    pred_kernel<<<(NN + 127) / 128, 128>>>(h2, W_pred, b_pred, logp, NN);
    // 8. x3 = h2 @ W2^T
    sgemm_kernel<<<gemm_grid(NN, HID), 256>>>(h2, W2T, nullptr, x3, NN, HID, OUTD);
    // 9. h3 = elu(aggregate(x3))  (reuses alpha)
    agg_elu_kernel<<<NN, 128>>>(x3, src, alpha, h3);
    // 10. h4 = h3 @ W1^T
    sgemm_kernel<<<gemm_grid(NN, DDIM), 256>>>(h3, W1T, nullptr, h4, NN, DDIM, HID);
    // 11. elu in place
    elu_kernel<<<(NN * DDIM + 255) / 256, 256>>>(h4, NN * DDIM);
    // 12. out = elu(h4) @ W_dec + b_dec  (output 1)
    sgemm_kernel<<<gemm_grid(NN, IN_DIM), 256>>>(h4, W_dec, b_dec, outm, NN, IN_DIM, DDIM);
}

// round 3
// speedup vs baseline: 4.7538x; 4.7538x over previous
#include <cuda_runtime.h>
#include <cuda_bf16.h>
#include <math.h>
#include <stdint.h>

// ---------------- problem constants ----------------
#define NN      30000
#define IN_DIM  3000
#define DDIM    512
#define HID     512
#define OUTD    30
#define PREDD   20
#define DEG     10
#define EDGES   (NN*DEG)
#define NEG_SLOPE 0.2f

// ---------------- scratch ----------------
__device__ float g_de [NN*DDIM];
__device__ float g_x1 [NN*HID];
__device__ float g_h1 [NN*HID];
__device__ float g_x3 [NN*HID];
__device__ float g_h3 [NN*HID];
__device__ float g_h4 [NN*DDIM];
__device__ float g_a1s[NN];
__device__ float g_a1d[NN];
__device__ float g_alpha[EDGES];
__device__ float g_W1T[HID*DDIM];
__device__ float g_W2T[OUTD*HID];

// =====================================================================
// TF32 tensor-core GEMM: C[M,N] = A[M,K] @ B[K,N] (+bias)
// block tile 128x128, BK=32, 8 warps (2x4), warp tile 64x32,
// mma.sync.m16n8k8.tf32, cp.async double-buffered.
// smem: As[2][128][36], Bs[2][32][136]  (padding -> conflict-free frags)
// =====================================================================
#define GA_STRIDE 36
#define GB_STRIDE 136
#define GSMEM_FLOATS (2*128*GA_STRIDE + 2*32*GB_STRIDE)

__device__ __forceinline__ uint32_t f2tf32(float f) {
    uint32_t u;
    asm("cvt.rna.tf32.f32 %0, %1;" : "=r"(u) : "f"(f));
    return u;
}

__device__ __forceinline__ void cp16(uint32_t dst, const float* src, int sz) {
    asm volatile("cp.async.ca.shared.global [%0], [%1], 16, %2;\n"
                 :: "r"(dst), "l"(src), "r"(sz));
}

__device__ __forceinline__ void tf32_load_tile(
    const float* __restrict__ A, const float* __restrict__ B,
    float* As, float* Bs, int stage, int kt,
    int row0, int col0, int M, int N, int K, int tid)
{
    const int k0 = kt << 5;
    float* Asb = As + stage * 128 * GA_STRIDE;
    float* Bsb = Bs + stage * 32 * GB_STRIDE;
    #pragma unroll
    for (int it = 0; it < 4; it++) {
        int idx = tid + it * 256;
        int r = idx >> 3, c4 = (idx & 7) << 2;
        int gr = row0 + r, gc = k0 + c4;
        uint32_t dst = (uint32_t)__cvta_generic_to_shared(&Asb[r * GA_STRIDE + c4]);
        int sz = (gr < M && gc < K) ? 16 : 0;
        cp16(dst, A + (size_t)gr * K + gc, sz);
    }
    #pragma unroll
    for (int it = 0; it < 4; it++) {
        int idx = tid + it * 256;
        int r = idx >> 5, c4 = (idx & 31) << 2;
        int gr = k0 + r, gc = col0 + c4;
        uint32_t dst = (uint32_t)__cvta_generic_to_shared(&Bsb[r * GB_STRIDE + c4]);
        int sz = (gr < K && gc < N) ? 16 : 0;
        cp16(dst, B + (size_t)gr * N + gc, sz);
    }
}

__global__ __launch_bounds__(256, 2) void tf32_gemm_kernel(
    const float* __restrict__ A, const float* __restrict__ B,
    const float* __restrict__ bias, float* __restrict__ C,
    int M, int N, int K)
{
    extern __shared__ float sm[];
    float* As = sm;
    float* Bs = sm + 2 * 128 * GA_STRIDE;

    const int tid  = threadIdx.x;
    const int lane = tid & 31;
    const int warp = tid >> 5;
    const int wm   = warp >> 2;      // 0..1
    const int wn   = warp & 3;       // 0..3
    const int row0 = blockIdx.y * 128;
    const int col0 = blockIdx.x * 128;
    const int lr   = lane >> 2;      // 0..7
    const int lc   = lane & 3;       // 0..3

    float acc[4][4][4];
    #pragma unroll
    for (int i = 0; i < 4; i++)
        #pragma unroll
        for (int j = 0; j < 4; j++)
            #pragma unroll
            for (int q = 0; q < 4; q++) acc[i][j][q] = 0.f;

    const int nk = (K + 31) >> 5;

    tf32_load_tile(A, B, As, Bs, 0, 0, row0, col0, M, N, K, tid);
    asm volatile("cp.async.commit_group;\n");

    for (int kt = 0; kt < nk; kt++) {
        if (kt + 1 < nk) {
            tf32_load_tile(A, B, As, Bs, (kt + 1) & 1, kt + 1, row0, col0, M, N, K, tid);
            asm volatile("cp.async.commit_group;\n");
            asm volatile("cp.async.wait_group 1;\n");
        } else {
            asm volatile("cp.async.wait_group 0;\n");
        }
        __syncthreads();

        const float* Asb = As + (kt & 1) * 128 * GA_STRIDE;
        const float* Bsb = Bs + (kt & 1) * 32 * GB_STRIDE;

        #pragma unroll
        for (int ks = 0; ks < 4; ks++) {
            const int kk = ks << 3;
            uint32_t a[4][4], b[4][2];
            #pragma unroll
            for (int ti = 0; ti < 4; ti++) {
                int rb = wm * 64 + ti * 16 + lr;
                int kc = kk + lc;
                a[ti][0] = f2tf32(Asb[rb * GA_STRIDE + kc]);
                a[ti][1] = f2tf32(Asb[(rb + 8) * GA_STRIDE + kc]);
                a[ti][2] = f2tf32(Asb[rb * GA_STRIDE + kc + 4]);
                a[ti][3] = f2tf32(Asb[(rb + 8) * GA_STRIDE + kc + 4]);
            }
            #pragma unroll
            for (int tj = 0; tj < 4; tj++) {
                int cb = wn * 32 + tj * 8 + lr;
                int kr = kk + lc;
                b[tj][0] = f2tf32(Bsb[kr * GB_STRIDE + cb]);
                b[tj][1] = f2tf32(Bsb[(kr + 4) * GB_STRIDE + cb]);
            }
            #pragma unroll
            for (int ti = 0; ti < 4; ti++)
                #pragma unroll
                for (int tj = 0; tj < 4; tj++) {
                    asm volatile(
                        "mma.sync.aligned.m16n8k8.row.col.f32.tf32.tf32.f32 "
                        "{%0,%1,%2,%3}, {%4,%5,%6,%7}, {%8,%9}, {%0,%1,%2,%3};\n"
                        : "+f"(acc[ti][tj][0]), "+f"(acc[ti][tj][1]),
                          "+f"(acc[ti][tj][2]), "+f"(acc[ti][tj][3])
                        : "r"(a[ti][0]), "r"(a[ti][1]), "r"(a[ti][2]), "r"(a[ti][3]),
                          "r"(b[tj][0]), "r"(b[tj][1]));
                }
        }
        __syncthreads();
    }

    // epilogue
    #pragma unroll
    for (int ti = 0; ti < 4; ti++) {
        int r0 = row0 + wm * 64 + ti * 16 + lr;
        int r1 = r0 + 8;
        #pragma unroll
        for (int tj = 0; tj < 4; tj++) {
            int c = col0 + wn * 32 + tj * 8 + (lc << 1);
            float bv0 = 0.f, bv1 = 0.f;
            if (bias) {
                if (c < N)     bv0 = bias[c];
                if (c + 1 < N) bv1 = bias[c + 1];
            }
            if (r0 < M) {
                if (c < N)     C[(size_t)r0 * N + c]     = acc[ti][tj][0] + bv0;
                if (c + 1 < N) C[(size_t)r0 * N + c + 1] = acc[ti][tj][1] + bv1;
            }
            if (r1 < M) {
                if (c < N)     C[(size_t)r1 * N + c]     = acc[ti][tj][2] + bv0;
                if (c + 1 < N) C[(size_t)r1 * N + c + 1] = acc[ti][tj][3] + bv1;
            }
        }
    }
}

// ---------------- fp32 tiled SGEMM (for the tiny GEMMs) --------------------
#define BM 128
#define BN 128
#define BK 8
#define TM 8
#define TN 8

__global__ __launch_bounds__(256) void sgemm_kernel(
    const float* __restrict__ A, const float* __restrict__ B,
    const float* __restrict__ bias, float* __restrict__ C,
    int M, int N, int K)
{
    __shared__ float As[BK][BM];
    __shared__ float Bs[BK][BN + 4];

    const int tid  = threadIdx.x;
    const int row0 = blockIdx.y * BM;
    const int col0 = blockIdx.x * BN;
    const int trow = (tid >> 4) * TM;
    const int tcol = (tid & 15) * TN;

    float acc[TM][TN];
    #pragma unroll
    for (int i = 0; i < TM; i++)
        #pragma unroll
        for (int j = 0; j < TN; j++) acc[i][j] = 0.f;

    for (int k0 = 0; k0 < K; k0 += BK) {
        #pragma unroll
        for (int s = 0; s < 4; s++) {
            int idx = tid + s * 256;
            int r = idx >> 3, c = idx & 7;
            int gr = row0 + r, gc = k0 + c;
            As[c][r] = (gr < M && gc < K) ? A[(size_t)gr * K + gc] : 0.f;
        }
        #pragma unroll
        for (int s = 0; s < 4; s++) {
            int idx = tid + s * 256;
            int r = idx >> 7, c = idx & 127;
            int gr = k0 + r, gc = col0 + c;
            Bs[r][c] = (gr < K && gc < N) ? B[(size_t)gr * N + gc] : 0.f;
        }
        __syncthreads();

        #pragma unroll
        for (int k = 0; k < BK; k++) {
            float a[TM], b[TN];
            #pragma unroll
            for (int i = 0; i < TM; i++) a[i] = As[k][trow + i];
            #pragma unroll
            for (int j = 0; j < TN; j++) b[j] = Bs[k][tcol + j];
            #pragma unroll
            for (int i = 0; i < TM; i++)
                #pragma unroll
                for (int j = 0; j < TN; j++)
                    acc[i][j] += a[i] * b[j];
        }
        __syncthreads();
    }

    #pragma unroll
    for (int i = 0; i < TM; i++) {
        int gr = row0 + trow + i;
        if (gr >= M) continue;
        #pragma unroll
        for (int j = 0; j < TN; j++) {
            int gc = col0 + tcol + j;
            if (gc >= N) continue;
            float v = acc[i][j];
            if (bias) v += bias[gc];
            C[(size_t)gr * N + gc] = v;
        }
    }
}

// ---------------- transpose ----------------
__global__ void transpose_kernel(const float* __restrict__ in,
                                 float* __restrict__ out, int R, int C)
{
    __shared__ float t[32][33];
    int c = blockIdx.x * 32 + threadIdx.x;
    int r = blockIdx.y * 32 + threadIdx.y;
    if (r < R && c < C) t[threadIdx.y][threadIdx.x] = in[r * C + c];
    __syncthreads();
    int r2 = blockIdx.x * 32 + threadIdx.y;
    int c2 = blockIdx.y * 32 + threadIdx.x;
    if (r2 < C && c2 < R) out[r2 * R + c2] = t[threadIdx.x][threadIdx.y];
}

// ---------------- attention logits ----------------
__global__ void row_logits_kernel(const float* __restrict__ x1,
                                  const float* __restrict__ att_s,
                                  const float* __restrict__ att_d,
                                  float* __restrict__ a1s,
                                  float* __restrict__ a1d, int n)
{
    int row = blockIdx.x * 8 + threadIdx.y;
    if (row >= n) return;
    int lane = threadIdx.x;
    float s = 0.f, d = 0.f;
    const float* xr = x1 + (size_t)row * HID;
    #pragma unroll 4
    for (int k = lane; k < HID; k += 32) {
        float v = xr[k];
        s += v * att_s[k];
        d += v * att_d[k];
    }
    #pragma unroll
    for (int o = 16; o > 0; o >>= 1) {
        s += __shfl_down_sync(0xffffffffu, s, o);
        d += __shfl_down_sync(0xffffffffu, d, o);
    }
    if (lane == 0) { a1s[row] = s; a1d[row] = d; }
}

// ---------------- edge softmax (contiguous segments) ----------------
__global__ void alpha_kernel(const int* __restrict__ src,
                             const int* __restrict__ dst,
                             const float* __restrict__ a1s,
                             const float* __restrict__ a1d,
                             float* __restrict__ alpha, int n)
{
    int i = blockIdx.x * 256 + threadIdx.x;
    if (i >= n) return;
    float e[DEG];
    float m = -1e30f;
    #pragma unroll
    for (int j = 0; j < DEG; j++) {
        int eidx = i * DEG + j;
        float v = a1s[src[eidx]] + a1d[dst[eidx]];
        v = (v > 0.f) ? v : NEG_SLOPE * v;
        e[j] = v;
        m = fmaxf(m, v);
    }
    float sum = 0.f;
    #pragma unroll
    for (int j = 0; j < DEG; j++) { e[j] = __expf(e[j] - m); sum += e[j]; }
    float inv = 1.f / sum;
    #pragma unroll
    for (int j = 0; j < DEG; j++) alpha[i * DEG + j] = e[j] * inv;
}

// ---------------- weighted aggregation + ELU ----------------
__global__ __launch_bounds__(128) void agg_elu_kernel(
    const float* __restrict__ x, const int* __restrict__ src,
    const float* __restrict__ alpha, float* __restrict__ out)
{
    int i = blockIdx.x;
    __shared__ int   ss[DEG];
    __shared__ float sa[DEG];
    if (threadIdx.x < DEG) {
        ss[threadIdx.x] = src[i * DEG + threadIdx.x];
        sa[threadIdx.x] = alpha[i * DEG + threadIdx.x];
    }
    __syncthreads();
    int c0 = threadIdx.x * 4;
    float a0 = 0.f, a1 = 0.f, a2 = 0.f, a3 = 0.f;
    #pragma unroll
    for (int j = 0; j < DEG; j++) {
        const float4 v = *(const float4*)&x[(size_t)ss[j] * HID + c0];
        float a = sa[j];
        a0 += a * v.x; a1 += a * v.y; a2 += a * v.z; a3 += a * v.w;
    }
    float4 r;
    r.x = (a0 > 0.f) ? a0 : expm1f(a0);
    r.y = (a1 > 0.f) ? a1 : expm1f(a1);
    r.z = (a2 > 0.f) ? a2 : expm1f(a2);
    r.w = (a3 > 0.f) ? a3 : expm1f(a3);
    *(float4*)&out[(size_t)i * HID + c0] = r;
}

// ---------------- prediction head ----------------
__global__ void pred_kernel(const float* __restrict__ h2,
                            const float* __restrict__ Wp,
                            const float* __restrict__ bp,
                            float* __restrict__ logp, int n)
{
    int i = blockIdx.x * 128 + threadIdx.x;
    if (i >= n) return;
    float h[OUTD];
    #pragma unroll
    for (int k = 0; k < OUTD; k++) h[k] = h2[(size_t)i * OUTD + k];
    float p[PREDD];
    float m = -1e30f;
    #pragma unroll
    for (int c = 0; c < PREDD; c++) {
        float s = bp[c];
        #pragma unroll
        for (int k = 0; k < OUTD; k++) s += h[k] * Wp[k * PREDD + c];
        p[c] = s;
        m = fmaxf(m, s);
    }
    float sum = 0.f;
    #pragma unroll
    for (int c = 0; c < PREDD; c++) sum += expf(p[c] - m);
    float lse = m + logf(sum);
    #pragma unroll
    for (int c = 0; c < PREDD; c++) logp[(size_t)i * PREDD + c] = p[c] - lse;
}

// ---------------- elementwise ELU ----------------
__global__ void elu_kernel(float* __restrict__ x, int n)
{
    int i = blockIdx.x * 256 + threadIdx.x;
    if (i >= n) return;
    float v = x[i];
    x[i] = (v > 0.f) ? v : expm1f(v);
}

// ---------------- launch ----------------
static inline dim3 gemm_grid(int M, int N) {
    return dim3((N + BN - 1) / BN, (M + BM - 1) / BM);
}
static inline dim3 tf32_grid(int M, int N) {
    return dim3((N + 127) / 128, (M + 127) / 128);
}

extern "C" void kernel_launch(void* const* d_in, const int* in_sizes, int n_in,
                              void* d_out, int out_size)
{
    const float* features = (const float*)d_in[0];
    const int*   edge     = (const int*)  d_in[1];
    const float* W_enc    = (const float*)d_in[2];
    const float* b_enc    = (const float*)d_in[3];
    const float* W1       = (const float*)d_in[4];
    const float* att_src  = (const float*)d_in[5];
    const float* att_dst  = (const float*)d_in[6];
    const float* W2       = (const float*)d_in[7];
    const float* W_pred   = (const float*)d_in[8];
    const float* b_pred   = (const float*)d_in[9];
    const float* W_dec    = (const float*)d_in[10];
    const float* b_dec    = (const float*)d_in[11];

    const int* src = edge;
    const int* dst = edge + EDGES;

    float* out  = (float*)d_out;
    float* h2   = out;
    float* outm = out + (size_t)NN * OUTD;
    float* logp = out + (size_t)NN * OUTD + (size_t)NN * IN_DIM;

    float *de, *x1, *h1, *x3, *h3, *h4, *a1s, *a1d, *alpha, *W1T, *W2T;
    cudaGetSymbolAddress((void**)&de,    g_de);
    cudaGetSymbolAddress((void**)&x1,    g_x1);
    cudaGetSymbolAddress((void**)&h1,    g_h1);
    cudaGetSymbolAddress((void**)&x3,    g_x3);
    cudaGetSymbolAddress((void**)&h3,    g_h3);
    cudaGetSymbolAddress((void**)&h4,    g_h4);
    cudaGetSymbolAddress((void**)&a1s,   g_a1s);
    cudaGetSymbolAddress((void**)&a1d,   g_a1d);
    cudaGetSymbolAddress((void**)&alpha, g_alpha);
    cudaGetSymbolAddress((void**)&W1T,   g_W1T);
    cudaGetSymbolAddress((void**)&W2T,   g_W2T);

    static int smem_set = 0;
    const int GSMEM_BYTES = GSMEM_FLOATS * 4;
    if (!smem_set) {
        cudaFuncSetAttribute(tf32_gemm_kernel,
                             cudaFuncAttributeMaxDynamicSharedMemorySize, GSMEM_BYTES);
        smem_set = 1;
    }

    transpose_kernel<<<dim3((HID + 31) / 32, (DDIM + 31) / 32), dim3(32, 32)>>>(W1, W1T, DDIM, HID);
    transpose_kernel<<<dim3((OUTD + 31) / 32, (HID + 31) / 32), dim3(32, 32)>>>(W2, W2T, HID, OUTD);

    // 1. de = features @ W_enc + b_enc            [30000,512] K=3000
    tf32_gemm_kernel<<<tf32_grid(NN, DDIM), 256, GSMEM_BYTES>>>(features, W_enc, b_enc, de, NN, DDIM, IN_DIM);
    // 2. x1 = de @ W1                             [30000,512] K=512
    tf32_gemm_kernel<<<tf32_grid(NN, HID), 256, GSMEM_BYTES>>>(de, W1, nullptr, x1, NN, HID, DDIM);
    // 3. attention logits
    row_logits_kernel<<<(NN + 7) / 8, dim3(32, 8)>>>(x1, att_src, att_dst, a1s, a1d, NN);
    // 4. edge softmax
    alpha_kernel<<<(NN + 255) / 256, 256>>>(src, dst, a1s, a1d, alpha, NN);
    // 5. h1 = elu(agg(x1))
    agg_elu_kernel<<<NN, 128>>>(x1, src, alpha, h1);
    // 6. h2 = h1 @ W2  (N=30, fp32 path)
    sgemm_kernel<<<gemm_grid(NN, OUTD), 256>>>(h1, W2, nullptr, h2, NN, OUTD, HID);
    // 7. log-softmax head
    pred_kernel<<<(NN + 127) / 128, 128>>>(h2, W_pred, b_pred, logp, NN);
    // 8. x3 = h2 @ W2^T  (K=30, fp32 path)
    sgemm_kernel<<<gemm_grid(NN, HID), 256>>>(h2, W2T, nullptr, x3, NN, HID, OUTD);
    // 9. h3 = elu(agg(x3))
    agg_elu_kernel<<<NN, 128>>>(x3, src, alpha, h3);
    // 10. h4 = h3 @ W1^T                          [30000,512] K=512
    tf32_gemm_kernel<<<tf32_grid(NN, DDIM), 256, GSMEM_BYTES>>>(h3, W1T, nullptr, h4, NN, DDIM, HID);
    // 11. elu in place
    elu_kernel<<<(NN * DDIM + 255) / 256, 256>>>(h4, NN * DDIM);
    // 12. out = elu(h4) @ W_dec + b_dec           [30000,3000] K=512
    tf32_gemm_kernel<<<tf32_grid(NN, IN_DIM), 256, GSMEM_BYTES>>>(h4, W_dec, b_dec, outm, NN, IN_DIM, DDIM);
}